// round 2
// baseline (speedup 1.0000x reference)
#include <cuda_runtime.h>
#include <cuda_bf16.h>

// Problem constants
#define B_ROWS   65536
#define FDIM     512
#define WARPS_PER_BLOCK 8
#define THREADS_PER_BLOCK (WARPS_PER_BLOCK * 32)
#define NUM_BLOCKS (B_ROWS / WARPS_PER_BLOCK)   // 8192

// Deterministic reduction scratch (no allocation allowed)
__device__ float g_partial[NUM_BLOCKS];

// Kernel 1: per-row gathered dot product + tanh + smooth-L1, per-block loss partial
__global__ __launch_bounds__(THREADS_PER_BLOCK)
void predict_kernel(const float* __restrict__ input,
                    const float* __restrict__ factor,
                    const int* __restrict__ label,     // int32! (JAX x64 disabled)
                    const float* __restrict__ centers,
                    float* __restrict__ out,           // out[0]=loss, out[1..B]=predict_a
                    int out_size)
{
    __shared__ float s_loss[WARPS_PER_BLOCK];

    const int warp_in_block = threadIdx.x >> 5;
    const int lane = threadIdx.x & 31;
    const int row = blockIdx.x * WARPS_PER_BLOCK + warp_in_block;

    const int lab = label[row];

    const float4* __restrict__ in4 = reinterpret_cast<const float4*>(input + (size_t)row * FDIM);
    const float4* __restrict__ c4  = reinterpret_cast<const float4*>(centers + (size_t)lab * FDIM);

    float acc = 0.0f;
#pragma unroll
    for (int i = 0; i < FDIM / (32 * 4); i++) {   // 4 iterations
        float4 a = in4[lane + i * 32];
        float4 c = c4[lane + i * 32];
        acc = fmaf(a.x, c.x, acc);
        acc = fmaf(a.y, c.y, acc);
        acc = fmaf(a.z, c.z, acc);
        acc = fmaf(a.w, c.w, acc);
    }

    // warp reduce
#pragma unroll
    for (int off = 16; off > 0; off >>= 1)
        acc += __shfl_xor_sync(0xFFFFFFFFu, acc, off);

    if (lane == 0) {
        float p = 12.0f * tanhf(acc);
        if (1 + row < out_size) out[1 + row] = p;
        float d = p - factor[row];
        float ad = fabsf(d);
        float l = (ad < 1.0f) ? 0.5f * d * d : (ad - 0.5f);
        s_loss[warp_in_block] = l;
    }
    __syncthreads();

    if (threadIdx.x == 0) {
        float s = 0.0f;
#pragma unroll
        for (int w = 0; w < WARPS_PER_BLOCK; w++) s += s_loss[w];
        g_partial[blockIdx.x] = s;
    }
}

// Kernel 2: deterministic single-block reduction of 8192 partials -> loss mean
__global__ __launch_bounds__(1024)
void reduce_kernel(float* __restrict__ out)
{
    __shared__ float s[1024];
    float acc = 0.0f;
#pragma unroll
    for (int i = 0; i < NUM_BLOCKS / 1024; i++)
        acc += g_partial[threadIdx.x + i * 1024];
    s[threadIdx.x] = acc;
    __syncthreads();
#pragma unroll
    for (int stride = 512; stride > 0; stride >>= 1) {
        if (threadIdx.x < stride) s[threadIdx.x] += s[threadIdx.x + stride];
        __syncthreads();
    }
    if (threadIdx.x == 0)
        out[0] = s[0] * (1.0f / (float)B_ROWS);
}

extern "C" void kernel_launch(void* const* d_in, const int* in_sizes, int n_in,
                              void* d_out, int out_size)
{
    const float* input   = (const float*)d_in[0];
    const float* factor  = (const float*)d_in[1];
    const int*   label   = (const int*)d_in[2];
    const float* centers = (const float*)d_in[3];
    float* out = (float*)d_out;

    predict_kernel<<<NUM_BLOCKS, THREADS_PER_BLOCK>>>(input, factor, label, centers, out, out_size);
    reduce_kernel<<<1, 1024>>>(out);
}

// round 3
// speedup vs baseline: 1.0904x; 1.0904x over previous
#include <cuda_runtime.h>
#include <cuda_bf16.h>

// Problem constants
#define B_ROWS   65536
#define FDIM     512
#define WARPS_PER_BLOCK 8
#define THREADS_PER_BLOCK (WARPS_PER_BLOCK * 32)
#define NUM_BLOCKS (B_ROWS / WARPS_PER_BLOCK)   // 8192

// Deterministic reduction scratch (no allocation allowed)
__device__ float g_partial[NUM_BLOCKS];
__device__ unsigned int g_count;   // zero-initialized; last block resets it to 0

__global__ __launch_bounds__(THREADS_PER_BLOCK)
void predict_kernel(const float* __restrict__ input,
                    const float* __restrict__ factor,
                    const int* __restrict__ label,     // int32 (JAX x64 disabled)
                    const float* __restrict__ centers,
                    float* __restrict__ out,           // out[0]=loss, out[1..B]=predict_a
                    int out_size)
{
    __shared__ float s_loss[WARPS_PER_BLOCK];
    __shared__ bool  s_is_last;

    const int warp_in_block = threadIdx.x >> 5;
    const int lane = threadIdx.x & 31;
    const int row = blockIdx.x * WARPS_PER_BLOCK + warp_in_block;

    const int lab = label[row];

    const float4* __restrict__ in4 = reinterpret_cast<const float4*>(input + (size_t)row * FDIM);
    const float4* __restrict__ c4  = reinterpret_cast<const float4*>(centers + (size_t)lab * FDIM);

    float acc = 0.0f;
#pragma unroll
    for (int i = 0; i < FDIM / (32 * 4); i++) {   // 4 iterations
        float4 a = __ldcs(&in4[lane + i * 32]);   // streaming: read-once, evict-first
        float4 c = __ldg(&c4[lane + i * 32]);     // cached: heavy reuse (2.66 MB)
        acc = fmaf(a.x, c.x, acc);
        acc = fmaf(a.y, c.y, acc);
        acc = fmaf(a.z, c.z, acc);
        acc = fmaf(a.w, c.w, acc);
    }

    // warp reduce
#pragma unroll
    for (int off = 16; off > 0; off >>= 1)
        acc += __shfl_xor_sync(0xFFFFFFFFu, acc, off);

    if (lane == 0) {
        float p = 12.0f * tanhf(acc);
        if (1 + row < out_size) out[1 + row] = p;
        float d = p - factor[row];
        float ad = fabsf(d);
        float l = (ad < 1.0f) ? 0.5f * d * d : (ad - 0.5f);
        s_loss[warp_in_block] = l;
    }
    __syncthreads();

    if (threadIdx.x == 0) {
        float s = 0.0f;
#pragma unroll
        for (int w = 0; w < WARPS_PER_BLOCK; w++) s += s_loss[w];
        g_partial[blockIdx.x] = s;
        __threadfence();
        unsigned int old = atomicAdd(&g_count, 1u);
        s_is_last = (old == NUM_BLOCKS - 1);
    }
    __syncthreads();

    // Last-arriving block performs the final reduction in a FIXED order
    // (deterministic regardless of which block arrives last).
    if (s_is_last) {
        __shared__ float s_red[THREADS_PER_BLOCK];
        float acc2 = 0.0f;
#pragma unroll
        for (int i = 0; i < NUM_BLOCKS / THREADS_PER_BLOCK; i++)       // 32 each
            acc2 += g_partial[threadIdx.x + i * THREADS_PER_BLOCK];
        s_red[threadIdx.x] = acc2;
        __syncthreads();
#pragma unroll
        for (int stride = THREADS_PER_BLOCK / 2; stride > 0; stride >>= 1) {
            if (threadIdx.x < stride) s_red[threadIdx.x] += s_red[threadIdx.x + stride];
            __syncthreads();
        }
        if (threadIdx.x == 0) {
            out[0] = s_red[0] * (1.0f / (float)B_ROWS);
            __threadfence();
            g_count = 0;   // reset for next graph replay
        }
    }
}

extern "C" void kernel_launch(void* const* d_in, const int* in_sizes, int n_in,
                              void* d_out, int out_size)
{
    const float* input   = (const float*)d_in[0];
    const float* factor  = (const float*)d_in[1];
    const int*   label   = (const int*)d_in[2];
    const float* centers = (const float*)d_in[3];
    float* out = (float*)d_out;

    predict_kernel<<<NUM_BLOCKS, THREADS_PER_BLOCK>>>(input, factor, label, centers, out, out_size);
}